// round 1
// baseline (speedup 1.0000x reference)
#include <cuda_runtime.h>
#include <cuda_bf16.h>
#include <math.h>

#define NN 50000
#define EMAX 800000

// ---------------- device scratch (no allocation allowed) ----------------
__device__ float g_dis[NN];
__device__ int   g_count[NN];
__device__ int   g_fill[NN];
__device__ int   g_rowptr[NN + 1];
__device__ int   g_bsum[256];
__device__ int   g_boff[256];
__device__ int   g_csrc[EMAX];
__device__ float g_cw[EMAX];
__device__ float g_bufA[(size_t)NN * 256];  // GEMM output h
__device__ float g_bufB[(size_t)NN * 256];  // aggregated (relu'd) features

// ---------------- small helpers ----------------
__global__ void zero_out_kernel(float* out) { out[0] = 0.0f; }

__global__ void count_init_kernel() {
    int i = blockIdx.x * blockDim.x + threadIdx.x;
    if (i < NN) { g_count[i] = 0; g_fill[i] = 0; }
}

__global__ void count_edges_kernel(const int* __restrict__ dst, int E) {
    int e = blockIdx.x * blockDim.x + threadIdx.x;
    if (e < E) atomicAdd(&g_count[dst[e]], 1);
}

__global__ void dis_kernel() {
    int i = blockIdx.x * blockDim.x + threadIdx.x;
    if (i < NN) g_dis[i] = rsqrtf((float)g_count[i] + 1.0f);
}

// ---------------- exclusive scan of g_count -> g_rowptr ----------------
__global__ void scan_block_kernel() {
    __shared__ int sd[256];
    int tid = threadIdx.x;
    int i = blockIdx.x * 256 + tid;
    int v = (i < NN) ? g_count[i] : 0;
    sd[tid] = v;
    __syncthreads();
    for (int off = 1; off < 256; off <<= 1) {
        int t = (tid >= off) ? sd[tid - off] : 0;
        __syncthreads();
        sd[tid] += t;
        __syncthreads();
    }
    if (i < NN) g_rowptr[i] = sd[tid] - v;   // in-block exclusive
    if (tid == 255) g_bsum[blockIdx.x] = sd[255];
}

__global__ void scan_tops_kernel(int nb) {
    __shared__ int sd[256];
    int tid = threadIdx.x;
    int v = (tid < nb) ? g_bsum[tid] : 0;
    sd[tid] = v;
    __syncthreads();
    for (int off = 1; off < 256; off <<= 1) {
        int t = (tid >= off) ? sd[tid - off] : 0;
        __syncthreads();
        sd[tid] += t;
        __syncthreads();
    }
    g_boff[tid] = sd[tid] - v;               // exclusive block offsets
}

__global__ void scan_add_kernel(int E) {
    int i = blockIdx.x * 256 + threadIdx.x;
    if (i < NN) g_rowptr[i] += g_boff[blockIdx.x];
    if (i == 0) g_rowptr[NN] = E;
}

__global__ void fill_csr_kernel(const int* __restrict__ src,
                                const int* __restrict__ dst, int E) {
    int e = blockIdx.x * blockDim.x + threadIdx.x;
    if (e >= E) return;
    int d = dst[e];
    int s = src[e];
    int pos = g_rowptr[d] + atomicAdd(&g_fill[d], 1);
    g_csrc[pos] = s;
    g_cw[pos] = g_dis[s] * g_dis[d];
}

// ---------------- GEMM: C[n,M] = A[n,K] @ B[K,M], fp32 ----------------
// 64x64 block tile, 16 K-tile, 256 threads, 4x4 microtile.
__global__ __launch_bounds__(256) void gemm_kernel(
    const float* __restrict__ A, const float* __restrict__ B,
    float* __restrict__ C, int n, int K, int M) {
    __shared__ __align__(16) float As[16][64];
    __shared__ __align__(16) float Bs[16][64];

    int tid = threadIdx.x;
    int tx = tid & 15;          // 0..15 -> cols
    int ty = tid >> 4;          // 0..15 -> rows
    int rowBase = blockIdx.x * 64;
    int colBase = blockIdx.y * 64;

    int aRow = tid >> 2;        // 0..63
    int aK4  = (tid & 3) * 4;   // 0,4,8,12
    int bK   = tid >> 4;        // 0..15
    int bC   = (tid & 15) * 4;  // 0..60

    float acc[4][4] = {};

    for (int k0 = 0; k0 < K; k0 += 16) {
        // load A tile (64 rows x 16 k), transposed into As[k][row]
        float4 av = make_float4(0.f, 0.f, 0.f, 0.f);
        int gr = rowBase + aRow;
        if (gr < n) av = *(const float4*)(A + (size_t)gr * K + k0 + aK4);
        As[aK4 + 0][aRow] = av.x;
        As[aK4 + 1][aRow] = av.y;
        As[aK4 + 2][aRow] = av.z;
        As[aK4 + 3][aRow] = av.w;
        // load B tile (16 k x 64 cols)
        float4 bv = *(const float4*)(B + (size_t)(k0 + bK) * M + colBase + bC);
        *(float4*)&Bs[bK][bC] = bv;
        __syncthreads();

#pragma unroll
        for (int kk = 0; kk < 16; kk++) {
            float4 a4 = *(const float4*)&As[kk][ty * 4];
            float4 b4 = *(const float4*)&Bs[kk][tx * 4];
            float a[4] = {a4.x, a4.y, a4.z, a4.w};
            float b[4] = {b4.x, b4.y, b4.z, b4.w};
#pragma unroll
            for (int i = 0; i < 4; i++)
#pragma unroll
                for (int j = 0; j < 4; j++)
                    acc[i][j] = fmaf(a[i], b[j], acc[i][j]);
        }
        __syncthreads();
    }

#pragma unroll
    for (int i = 0; i < 4; i++) {
        int r = rowBase + ty * 4 + i;
        if (r < n) {
            float4 v = make_float4(acc[i][0], acc[i][1], acc[i][2], acc[i][3]);
            *(float4*)(C + (size_t)r * M + colBase + tx * 4) = v;
        }
    }
}

// ---------------- aggregation (gather / segment-sum), fused bias+selfloop+relu
template <int M>
__global__ __launch_bounds__(256) void agg_kernel(
    const float* __restrict__ h, const float* __restrict__ bias,
    float* __restrict__ out) {
    int warp = (blockIdx.x * blockDim.x + threadIdx.x) >> 5;
    int lane = threadIdx.x & 31;
    if (warp >= NN) return;
    constexpr int U = M / 32;

    float d = g_dis[warp];
    float dd = d * d;
    const float* hi = h + (size_t)warp * M;
    float acc[U];
#pragma unroll
    for (int j = 0; j < U; j++)
        acc[j] = hi[lane + 32 * j] * dd + bias[lane + 32 * j];

    int e0 = g_rowptr[warp];
    int e1 = g_rowptr[warp + 1];
    for (int e = e0; e < e1; e++) {
        int s = g_csrc[e];
        float w = g_cw[e];
        const float* hs = h + (size_t)s * M;
#pragma unroll
        for (int j = 0; j < U; j++)
            acc[j] = fmaf(w, __ldg(&hs[lane + 32 * j]), acc[j]);
    }

    float* oi = out + (size_t)warp * M;
#pragma unroll
    for (int j = 0; j < U; j++)
        oi[lane + 32 * j] = fmaxf(acc[j], 0.0f);
}

// ---------------- final reduction: sum(all elements)/64 ----------------
__global__ void reduce_kernel(const float* __restrict__ a, int total,
                              float* __restrict__ out) {
    float s = 0.0f;
    for (int i = blockIdx.x * blockDim.x + threadIdx.x; i < total;
         i += gridDim.x * blockDim.x)
        s += a[i];
#pragma unroll
    for (int o = 16; o; o >>= 1) s += __shfl_down_sync(0xFFFFFFFFu, s, o);
    __shared__ float ws[8];
    if ((threadIdx.x & 31) == 0) ws[threadIdx.x >> 5] = s;
    __syncthreads();
    if (threadIdx.x < 8) {
        float t = ws[threadIdx.x];
#pragma unroll
        for (int o = 4; o; o >>= 1) t += __shfl_down_sync(0xFFu, t, o);
        if (threadIdx.x == 0) atomicAdd(out, t * (1.0f / 64.0f));
    }
}

// ---------------- launcher ----------------
extern "C" void kernel_launch(void* const* d_in, const int* in_sizes, int n_in,
                              void* d_out, int out_size) {
    const float* x[3]  = {(const float*)d_in[0], (const float*)d_in[1],
                          (const float*)d_in[2]};
    const int*   ei[3] = {(const int*)d_in[3], (const int*)d_in[4],
                          (const int*)d_in[5]};
    const float* W1 = (const float*)d_in[6];
    const float* b1 = (const float*)d_in[7];
    const float* W2 = (const float*)d_in[8];
    const float* b2 = (const float*)d_in[9];
    const float* W3 = (const float*)d_in[10];
    const float* b3 = (const float*)d_in[11];
    float* out = (float*)d_out;

    float *pA, *pB;
    cudaGetSymbolAddress((void**)&pA, g_bufA);
    cudaGetSymbolAddress((void**)&pB, g_bufB);

    const int NB = (NN + 255) / 256;        // 196
    const int GX = (NN + 63) / 64;          // 782
    const int AGG_BLOCKS = (NN * 32 + 255) / 256;

    zero_out_kernel<<<1, 1>>>(out);

    for (int g = 0; g < 3; g++) {
        int E = in_sizes[3 + g] / 2;
        const int* src = ei[g];
        const int* dst = ei[g] + E;
        int EB = (E + 255) / 256;

        // degree + dis + CSR build (reused across all 3 layers)
        count_init_kernel<<<NB, 256>>>();
        count_edges_kernel<<<EB, 256>>>(dst, E);
        dis_kernel<<<NB, 256>>>();
        scan_block_kernel<<<NB, 256>>>();
        scan_tops_kernel<<<1, 256>>>(NB);
        scan_add_kernel<<<NB, 256>>>(E);
        fill_csr_kernel<<<EB, 256>>>(src, dst, E);

        // layer 1: 256 -> 256
        gemm_kernel<<<dim3(GX, 4), 256>>>(x[g], W1, pA, NN, 256, 256);
        agg_kernel<256><<<AGG_BLOCKS, 256>>>(pA, b1, pB);
        // layer 2: 256 -> 128
        gemm_kernel<<<dim3(GX, 2), 256>>>(pB, W2, pA, NN, 256, 128);
        agg_kernel<128><<<AGG_BLOCKS, 256>>>(pA, b2, pB);
        // layer 3: 128 -> 64
        gemm_kernel<<<dim3(GX, 1), 256>>>(pB, W3, pA, NN, 128, 64);
        agg_kernel<64><<<AGG_BLOCKS, 256>>>(pA, b3, pB);

        reduce_kernel<<<1184, 256>>>(pB, NN * 64, out);
    }
}

// round 5
// speedup vs baseline: 2.0316x; 2.0316x over previous
#include <cuda_runtime.h>
#include <cuda_bf16.h>
#include <math.h>
#include <stdint.h>

#define NN 50000
#define EMAX 800000

// ======================= device scratch =======================
__device__ float g_dis[NN];
__device__ int   g_count[NN];
__device__ int   g_fill[NN];
__device__ int   g_rowptr[NN + 1];
__device__ int   g_bsum[256];
__device__ int   g_boff[256];
__device__ int   g_csrc[EMAX];
__device__ float g_cw[EMAX];
__device__ __nv_bfloat16 g_h[(size_t)NN * 256];   // GEMM output
__device__ __nv_bfloat16 g_a[(size_t)NN * 256];   // agg output / GEMM input
__device__ __nv_bfloat16 g_Wt1[256 * 256];        // W^T bf16 [N,K]
__device__ __nv_bfloat16 g_Wt2[128 * 256];
__device__ __nv_bfloat16 g_Wt3[64 * 128];

// ======================= PTX wrappers =======================
__device__ __forceinline__ uint32_t smem_u32(const void* p) {
    uint32_t a;
    asm("{ .reg .u64 t; cvta.to.shared.u64 t, %1; cvt.u32.u64 %0, t; }"
        : "=r"(a) : "l"(p));
    return a;
}

__device__ __forceinline__ void ldsm_x4(uint32_t* r, uint32_t addr) {
    asm volatile(
        "ldmatrix.sync.aligned.m8n8.x4.shared.b16 {%0,%1,%2,%3}, [%4];"
        : "=r"(r[0]), "=r"(r[1]), "=r"(r[2]), "=r"(r[3]) : "r"(addr));
}

__device__ __forceinline__ void mma_bf16(float* d, const uint32_t* a,
                                         uint32_t b0, uint32_t b1) {
    asm volatile(
        "mma.sync.aligned.m16n8k16.row.col.f32.bf16.bf16.f32 "
        "{%0,%1,%2,%3}, {%4,%5,%6,%7}, {%8,%9}, {%0,%1,%2,%3};"
        : "+f"(d[0]), "+f"(d[1]), "+f"(d[2]), "+f"(d[3])
        : "r"(a[0]), "r"(a[1]), "r"(a[2]), "r"(a[3]), "r"(b0), "r"(b1));
}

// ======================= small helpers =======================
__global__ void zero_out_kernel(float* out) { out[0] = 0.0f; }

__global__ void count_init_kernel() {
    int i = blockIdx.x * blockDim.x + threadIdx.x;
    if (i < NN) { g_count[i] = 0; g_fill[i] = 0; }
}

__global__ void count_edges_kernel(const int* __restrict__ dst, int E) {
    int e = blockIdx.x * blockDim.x + threadIdx.x;
    if (e < E) atomicAdd(&g_count[dst[e]], 1);
}

__global__ void dis_kernel() {
    int i = blockIdx.x * blockDim.x + threadIdx.x;
    if (i < NN) g_dis[i] = rsqrtf((float)g_count[i] + 1.0f);
}

__global__ void scan_block_kernel() {
    __shared__ int sd[256];
    int tid = threadIdx.x;
    int i = blockIdx.x * 256 + tid;
    int v = (i < NN) ? g_count[i] : 0;
    sd[tid] = v;
    __syncthreads();
    for (int off = 1; off < 256; off <<= 1) {
        int t = (tid >= off) ? sd[tid - off] : 0;
        __syncthreads();
        sd[tid] += t;
        __syncthreads();
    }
    if (i < NN) g_rowptr[i] = sd[tid] - v;
    if (tid == 255) g_bsum[blockIdx.x] = sd[255];
}

__global__ void scan_tops_kernel(int nb) {
    __shared__ int sd[256];
    int tid = threadIdx.x;
    int v = (tid < nb) ? g_bsum[tid] : 0;
    sd[tid] = v;
    __syncthreads();
    for (int off = 1; off < 256; off <<= 1) {
        int t = (tid >= off) ? sd[tid - off] : 0;
        __syncthreads();
        sd[tid] += t;
        __syncthreads();
    }
    g_boff[tid] = sd[tid] - v;
}

__global__ void scan_add_kernel(int E) {
    int i = blockIdx.x * 256 + threadIdx.x;
    if (i < NN) g_rowptr[i] += g_boff[blockIdx.x];
    if (i == 0) g_rowptr[NN] = E;
}

__global__ void fill_csr_kernel(const int* __restrict__ src,
                                const int* __restrict__ dst, int E) {
    int e = blockIdx.x * blockDim.x + threadIdx.x;
    if (e >= E) return;
    int d = dst[e];
    int s = src[e];
    int pos = g_rowptr[d] + atomicAdd(&g_fill[d], 1);
    g_csrc[pos] = s;
    g_cw[pos] = g_dis[s] * g_dis[d];
}

// W [K,N] fp32 -> Wt [N,K] bf16
__global__ void wt_kernel(const float* __restrict__ W,
                          __nv_bfloat16* __restrict__ out, int K, int N) {
    int i = blockIdx.x * blockDim.x + threadIdx.x;
    if (i < N * K) {
        int nrow = i / K, k = i - nrow * K;
        out[i] = __float2bfloat16(W[k * N + nrow]);
    }
}

// ======================= HMMA GEMM =======================
// C[n,N](bf16) = A[n,K] @ Wt^T, Wt is [N,K] bf16 row-major (B col-major).
// CTA tile 128 rows x 64 cols, 8 warps in 4x2, warp tile 32x32.
// Full-K smem staging, padded layout (stride K+8).
template <bool AFP32, int K, int N>
__global__ __launch_bounds__(256) void gemm_mma_kernel(
    const void* __restrict__ Ain, const __nv_bfloat16* __restrict__ Wt,
    __nv_bfloat16* __restrict__ C, int n) {
    constexpr int LDS = K + 8;  // padded row stride (elements)
    extern __shared__ __nv_bfloat16 sm[];
    __nv_bfloat16* As = sm;                 // [128][LDS]
    __nv_bfloat16* Ws = sm + 128 * LDS;     // [64][LDS]

    int tid = threadIdx.x;
    int lane = tid & 31;
    int warp = tid >> 5;
    int rowBase = blockIdx.x * 128;
    int colBase = blockIdx.y * 64;
    int warpM = (warp >> 1) * 32;   // 0,32,64,96
    int warpN = (warp & 1) * 32;    // 0,32

    // ---- stage A (128 x K) ----
    {
        constexpr int K8 = K / 8;
        for (int v = tid; v < 128 * K8; v += 256) {
            int r = v / K8;
            int k0 = (v - r * K8) * 8;
            int gr = rowBase + r;
            uint4 val = make_uint4(0, 0, 0, 0);
            if (gr < n) {
                if (AFP32) {
                    const float4* ap =
                        (const float4*)((const float*)Ain + (size_t)gr * K + k0);
                    float4 f0 = ap[0], f1 = ap[1];
                    __nv_bfloat162 p0, p1, p2, p3;
                    p0.x = __float2bfloat16(f0.x); p0.y = __float2bfloat16(f0.y);
                    p1.x = __float2bfloat16(f0.z); p1.y = __float2bfloat16(f0.w);
                    p2.x = __float2bfloat16(f1.x); p2.y = __float2bfloat16(f1.y);
                    p3.x = __float2bfloat16(f1.z); p3.y = __float2bfloat16(f1.w);
                    val.x = *(uint32_t*)&p0; val.y = *(uint32_t*)&p1;
                    val.z = *(uint32_t*)&p2; val.w = *(uint32_t*)&p3;
                } else {
                    val = *(const uint4*)((const __nv_bfloat16*)Ain +
                                          (size_t)gr * K + k0);
                }
            }
            *(uint4*)(As + r * LDS + k0) = val;
        }
    }
    // ---- stage W (64 x K) ----
    {
        constexpr int K8 = K / 8;
        for (int v = tid; v < 64 * K8; v += 256) {
            int r = v / K8;
            int k0 = (v - r * K8) * 8;
            *(uint4*)(Ws + r * LDS + k0) =
                *(const uint4*)(Wt + (size_t)(colBase + r) * K + k0);
        }
    }
    __syncthreads();

    uint32_t sA = smem_u32(As);
    uint32_t sW = smem_u32(Ws);

    float acc[2][4][4] = {};  // [m-tile][n-tile][frag]

    int lr = lane & 15;        // 0..15
    int lc = (lane >> 4) * 8;  // 0 or 8

#pragma unroll
    for (int k0 = 0; k0 < K; k0 += 16) {
        uint32_t af[2][4], bf[2][4];
#pragma unroll
        for (int mt = 0; mt < 2; mt++) {
            uint32_t addr =
                sA + ((warpM + mt * 16 + lr) * LDS + k0 + lc) * 2;
            ldsm_x4(af[mt], addr);
        }
#pragma unroll
        for (int nh = 0; nh < 2; nh++) {
            uint32_t addr =
                sW + ((warpN + nh * 16 + lr) * LDS + k0 + lc) * 2;
            ldsm_x4(bf[nh], addr);  // non-trans: Ws is [n][k], k-contiguous
        }
        // bf[nh][0]=n0-7 k0-7, [1]=n8-15 k0-7, [2]=n0-7 k8-15, [3]=n8-15 k8-15
#pragma unroll
        for (int mt = 0; mt < 2; mt++) {
#pragma unroll
            for (int nh = 0; nh < 2; nh++) {
                mma_bf16(acc[mt][nh * 2 + 0], af[mt], bf[nh][0], bf[nh][2]);
                mma_bf16(acc[mt][nh * 2 + 1], af[mt], bf[nh][1], bf[nh][3]);
            }
        }
    }

    // ---- epilogue: fp32 -> bf16, direct global store ----
    int groupID = lane >> 2;
    int qcol = (lane & 3) * 2;
#pragma unroll
    for (int mt = 0; mt < 2; mt++) {
#pragma unroll
        for (int half = 0; half < 2; half++) {
            int row = rowBase + warpM + mt * 16 + groupID + half * 8;
            if (row < n) {
                uint32_t* orow = (uint32_t*)(C + (size_t)row * N + colBase);
#pragma unroll
                for (int nt = 0; nt < 4; nt++) {
                    __nv_bfloat162 b2;
                    b2.x = __float2bfloat16(acc[mt][nt][half * 2 + 0]);
                    b2.y = __float2bfloat16(acc[mt][nt][half * 2 + 1]);
                    orow[(warpN + nt * 8 + qcol) >> 1] = *(uint32_t*)&b2;
                }
            }
        }
    }
}

// ======================= aggregation (bf16 gather) =======================
template <int M>
__global__ __launch_bounds__(256) void agg_kernel(
    const __nv_bfloat16* __restrict__ h, const float* __restrict__ bias,
    __nv_bfloat16* __restrict__ out) {
    int warp = (blockIdx.x * blockDim.x + threadIdx.x) >> 5;
    int lane = threadIdx.x & 31;
    if (warp >= NN) return;
    constexpr int U = M / 64;  // bf16x2 units per lane

    float dv = g_dis[warp];
    float dd = dv * dv;
    const uint32_t* hi = (const uint32_t*)(h + (size_t)warp * M);
    float acc[2 * U];
#pragma unroll
    for (int j = 0; j < U; j++) {
        uint32_t u = hi[lane + 32 * j];
        float2 f = __bfloat1622float2(*(__nv_bfloat162*)&u);
        int c = 2 * (lane + 32 * j);
        acc[2 * j]     = f.x * dd + bias[c];
        acc[2 * j + 1] = f.y * dd + bias[c + 1];
    }

    int e0 = g_rowptr[warp];
    int e1 = g_rowptr[warp + 1];
    for (int e = e0; e < e1; e++) {
        int s = g_csrc[e];
        float w = g_cw[e];
        const uint32_t* hs = (const uint32_t*)(h + (size_t)s * M);
#pragma unroll
        for (int j = 0; j < U; j++) {
            uint32_t u = __ldg(&hs[lane + 32 * j]);
            float2 f = __bfloat1622float2(*(__nv_bfloat162*)&u);
            acc[2 * j]     = fmaf(w, f.x, acc[2 * j]);
            acc[2 * j + 1] = fmaf(w, f.y, acc[2 * j + 1]);
        }
    }

    uint32_t* oi = (uint32_t*)(out + (size_t)warp * M);
#pragma unroll
    for (int j = 0; j < U; j++) {
        __nv_bfloat162 b2;
        b2.x = __float2bfloat16(fmaxf(acc[2 * j], 0.0f));
        b2.y = __float2bfloat16(fmaxf(acc[2 * j + 1], 0.0f));
        oi[lane + 32 * j] = *(uint32_t*)&b2;
    }
}

// ======================= final reduction =======================
__global__ void reduce_kernel(const __nv_bfloat16* __restrict__ a, int total2,
                              float* __restrict__ out) {
    const uint32_t* p = (const uint32_t*)a;
    float s = 0.0f;
    for (int i = blockIdx.x * blockDim.x + threadIdx.x; i < total2;
         i += gridDim.x * blockDim.x) {
        uint32_t u = p[i];
        float2 f = __bfloat1622float2(*(__nv_bfloat162*)&u);
        s += f.x + f.y;
    }
#pragma unroll
    for (int o = 16; o; o >>= 1) s += __shfl_down_sync(0xFFFFFFFFu, s, o);
    __shared__ float ws[8];
    if ((threadIdx.x & 31) == 0) ws[threadIdx.x >> 5] = s;
    __syncthreads();
    if (threadIdx.x < 8) {
        float t = ws[threadIdx.x];
#pragma unroll
        for (int o = 4; o; o >>= 1) t += __shfl_down_sync(0xFFu, t, o);
        if (threadIdx.x == 0) atomicAdd(out, t * (1.0f / 64.0f));
    }
}

// ======================= launcher =======================
extern "C" void kernel_launch(void* const* d_in, const int* in_sizes, int n_in,
                              void* d_out, int out_size) {
    const float* x[3]  = {(const float*)d_in[0], (const float*)d_in[1],
                          (const float*)d_in[2]};
    const int*   ei[3] = {(const int*)d_in[3], (const int*)d_in[4],
                          (const int*)d_in[5]};
    const float* W1 = (const float*)d_in[6];
    const float* b1 = (const float*)d_in[7];
    const float* W2 = (const float*)d_in[8];
    const float* b2 = (const float*)d_in[9];
    const float* W3 = (const float*)d_in[10];
    const float* b3 = (const float*)d_in[11];
    float* out = (float*)d_out;

    __nv_bfloat16 *ph, *pa, *pw1, *pw2, *pw3;
    cudaGetSymbolAddress((void**)&ph, g_h);
    cudaGetSymbolAddress((void**)&pa, g_a);
    cudaGetSymbolAddress((void**)&pw1, g_Wt1);
    cudaGetSymbolAddress((void**)&pw2, g_Wt2);
    cudaGetSymbolAddress((void**)&pw3, g_Wt3);

    // dynamic smem: (128+64) * (K+8) * 2 bytes
    const int SM256 = 192 * (256 + 8) * 2;  // 101376
    const int SM128 = 192 * (128 + 8) * 2;  // 52224
    cudaFuncSetAttribute(gemm_mma_kernel<true, 256, 256>,
                         cudaFuncAttributeMaxDynamicSharedMemorySize, SM256);
    cudaFuncSetAttribute(gemm_mma_kernel<false, 256, 128>,
                         cudaFuncAttributeMaxDynamicSharedMemorySize, SM256);
    cudaFuncSetAttribute(gemm_mma_kernel<false, 128, 64>,
                         cudaFuncAttributeMaxDynamicSharedMemorySize, SM128);

    const int NB = (NN + 255) / 256;
    const int GB = (NN + 127) / 128;  // 391
    const int AGG_BLOCKS = (NN * 32 + 255) / 256;

    zero_out_kernel<<<1, 1>>>(out);
    wt_kernel<<<(256 * 256 + 255) / 256, 256>>>(W1, pw1, 256, 256);
    wt_kernel<<<(128 * 256 + 255) / 256, 256>>>(W2, pw2, 256, 128);
    wt_kernel<<<(64 * 128 + 255) / 256, 256>>>(W3, pw3, 128, 64);

    for (int g = 0; g < 3; g++) {
        int E = in_sizes[3 + g] / 2;
        const int* src = ei[g];
        const int* dst = ei[g] + E;
        int EB = (E + 255) / 256;

        count_init_kernel<<<NB, 256>>>();
        count_edges_kernel<<<EB, 256>>>(dst, E);
        dis_kernel<<<NB, 256>>>();
        scan_block_kernel<<<NB, 256>>>();
        scan_tops_kernel<<<1, 256>>>(NB);
        scan_add_kernel<<<NB, 256>>>(E);
        fill_csr_kernel<<<EB, 256>>>(src, dst, E);

        gemm_mma_kernel<true, 256, 256>
            <<<dim3(GB, 4), 256, SM256>>>(x[g], pw1, ph, NN);
        agg_kernel<256><<<AGG_BLOCKS, 256>>>(ph, b1, pa);
        gemm_mma_kernel<false, 256, 128>
            <<<dim3(GB, 2), 256, SM256>>>(pa, pw2, ph, NN);
        agg_kernel<128><<<AGG_BLOCKS, 256>>>(ph, b2, pa);
        gemm_mma_kernel<false, 128, 64>
            <<<dim3(GB, 1), 256, SM128>>>(pa, pw3, ph, NN);
        agg_kernel<64><<<AGG_BLOCKS, 256>>>(ph, b3, pa);

        reduce_kernel<<<1184, 256>>>(pa, NN * 32, out);
    }
}

// round 6
// speedup vs baseline: 2.3467x; 1.1551x over previous
#include <cuda_runtime.h>
#include <cuda_bf16.h>
#include <math.h>
#include <stdint.h>

#define NN 50000
#define EMAX 800000
#define AGG_BLKS 6250  // NN/8 warps-per-block

// ======================= device scratch (triplicated per graph) ==========
__device__ float g_dis[3][NN];
__device__ int   g_count[3][NN];
__device__ int   g_fill[3][NN];
__device__ int   g_rowptr[3][NN + 1];
__device__ int   g_bsum[3][256];
__device__ int   g_boff[3][256];
__device__ int   g_csrc[3][EMAX];
__device__ float g_cw[3][EMAX];
__device__ __nv_bfloat16 g_h[3][(size_t)NN * 256];   // GEMM output
__device__ __nv_bfloat16 g_a[3][(size_t)NN * 256];   // agg output / GEMM input
__device__ __nv_bfloat16 g_Wt1[256 * 256];           // W^T bf16 [N,K]
__device__ __nv_bfloat16 g_Wt2[128 * 256];
__device__ __nv_bfloat16 g_Wt3[64 * 128];
__device__ float g_part[3 * AGG_BLKS];               // layer-3 block partials

struct PtrsIn  { const void* a[3]; };
struct PtrsOut { void* o[3]; };
struct Edges   { const int* e[3]; int E[3]; };

// ======================= PTX wrappers =======================
__device__ __forceinline__ uint32_t smem_u32(const void* p) {
    uint32_t a;
    asm("{ .reg .u64 t; cvta.to.shared.u64 t, %1; cvt.u32.u64 %0, t; }"
        : "=r"(a) : "l"(p));
    return a;
}

__device__ __forceinline__ void ldsm_x4(uint32_t* r, uint32_t addr) {
    asm volatile(
        "ldmatrix.sync.aligned.m8n8.x4.shared.b16 {%0,%1,%2,%3}, [%4];"
        : "=r"(r[0]), "=r"(r[1]), "=r"(r[2]), "=r"(r[3]) : "r"(addr));
}

__device__ __forceinline__ void mma_bf16(float* d, const uint32_t* a,
                                         uint32_t b0, uint32_t b1) {
    asm volatile(
        "mma.sync.aligned.m16n8k16.row.col.f32.bf16.bf16.f32 "
        "{%0,%1,%2,%3}, {%4,%5,%6,%7}, {%8,%9}, {%0,%1,%2,%3};"
        : "+f"(d[0]), "+f"(d[1]), "+f"(d[2]), "+f"(d[3])
        : "r"(a[0]), "r"(a[1]), "r"(a[2]), "r"(a[3]), "r"(b0), "r"(b1));
}

// ======================= graph-prep kernels (z = graph) =======================
__global__ void count_init_kernel() {
    int i = blockIdx.x * blockDim.x + threadIdx.x;
    int z = blockIdx.z;
    if (i < NN) { g_count[z][i] = 0; g_fill[z][i] = 0; }
}

__global__ void count_edges_kernel(Edges eg) {
    int e = blockIdx.x * blockDim.x + threadIdx.x;
    int z = blockIdx.z;
    int E = eg.E[z];
    const int* dst = eg.e[z] + E;
    if (e < E) atomicAdd(&g_count[z][dst[e]], 1);
}

// block scan of g_count -> g_rowptr (partial) + dis = rsqrt(deg+1)
__global__ void scan_block_kernel() {
    __shared__ int sd[256];
    int tid = threadIdx.x;
    int z = blockIdx.z;
    int i = blockIdx.x * 256 + tid;
    int v = (i < NN) ? g_count[z][i] : 0;
    if (i < NN) g_dis[z][i] = rsqrtf((float)v + 1.0f);
    sd[tid] = v;
    __syncthreads();
    for (int off = 1; off < 256; off <<= 1) {
        int t = (tid >= off) ? sd[tid - off] : 0;
        __syncthreads();
        sd[tid] += t;
        __syncthreads();
    }
    if (i < NN) g_rowptr[z][i] = sd[tid] - v;
    if (tid == 255) g_bsum[z][blockIdx.x] = sd[255];
}

__global__ void scan_tops_kernel(int nb) {
    __shared__ int sd[256];
    int tid = threadIdx.x;
    int z = blockIdx.z;
    int v = (tid < nb) ? g_bsum[z][tid] : 0;
    sd[tid] = v;
    __syncthreads();
    for (int off = 1; off < 256; off <<= 1) {
        int t = (tid >= off) ? sd[tid - off] : 0;
        __syncthreads();
        sd[tid] += t;
        __syncthreads();
    }
    g_boff[z][tid] = sd[tid] - v;
}

__global__ void scan_add_kernel(Edges eg) {
    int i = blockIdx.x * 256 + threadIdx.x;
    int z = blockIdx.z;
    if (i < NN) g_rowptr[z][i] += g_boff[z][blockIdx.x];
    if (i == 0) g_rowptr[z][NN] = eg.E[z];
}

__global__ void fill_csr_kernel(Edges eg) {
    int e = blockIdx.x * blockDim.x + threadIdx.x;
    int z = blockIdx.z;
    int E = eg.E[z];
    if (e >= E) return;
    const int* src = eg.e[z];
    const int* dst = src + E;
    int d = dst[e];
    int s = src[e];
    int pos = g_rowptr[z][d] + atomicAdd(&g_fill[z][d], 1);
    g_csrc[z][pos] = s;
    g_cw[z][pos] = g_dis[z][s] * g_dis[z][d];
}

// all three W [K,N] fp32 -> Wt [N,K] bf16 in one launch
__global__ void wt_all_kernel(const float* W1, const float* W2,
                              const float* W3) {
    int i = blockIdx.x * blockDim.x + threadIdx.x;
    if (i < 65536) {  // Wt1: [256][256]
        int nrow = i >> 8, k = i & 255;
        g_Wt1[i] = __float2bfloat16(W1[k * 256 + nrow]);
    } else if (i < 98304) {  // Wt2: [128][256]
        int j = i - 65536;
        int nrow = j >> 8, k = j & 255;
        g_Wt2[j] = __float2bfloat16(W2[k * 128 + nrow]);
    } else if (i < 106496) {  // Wt3: [64][128]
        int j = i - 98304;
        int nrow = j >> 7, k = j & 127;
        g_Wt3[j] = __float2bfloat16(W3[k * 64 + nrow]);
    }
}

// ======================= HMMA GEMM =======================
// C[n,N](bf16) = A[n,K] @ Wt^T. CTA: 128 rows; A staged ONCE, then loop over
// N in 64-col chunks restaging only W. 8 warps 4x2, warp tile 32x32.
template <bool AFP32, int K, int N>
__global__ __launch_bounds__(256) void gemm_mma_kernel(
    PtrsIn A3, const __nv_bfloat16* __restrict__ Wt, PtrsOut C3, int n) {
    constexpr int LDS = K + 8;
    extern __shared__ __nv_bfloat16 sm[];
    __nv_bfloat16* As = sm;               // [128][LDS]
    __nv_bfloat16* Ws = sm + 128 * LDS;   // [64][LDS]

    int z = blockIdx.z;
    const void* Ain = A3.a[z];
    __nv_bfloat16* C = (__nv_bfloat16*)C3.o[z];

    int tid = threadIdx.x;
    int lane = tid & 31;
    int warp = tid >> 5;
    int rowBase = blockIdx.x * 128;
    int warpM = (warp >> 1) * 32;
    int warpN = (warp & 1) * 32;

    // ---- stage A (128 x K) once ----
    {
        constexpr int K8 = K / 8;
        for (int v = tid; v < 128 * K8; v += 256) {
            int r = v / K8;
            int k0 = (v - r * K8) * 8;
            int gr = rowBase + r;
            uint4 val = make_uint4(0, 0, 0, 0);
            if (gr < n) {
                if (AFP32) {
                    const float4* ap =
                        (const float4*)((const float*)Ain + (size_t)gr * K + k0);
                    float4 f0 = ap[0], f1 = ap[1];
                    __nv_bfloat162 p0, p1, p2, p3;
                    p0.x = __float2bfloat16(f0.x); p0.y = __float2bfloat16(f0.y);
                    p1.x = __float2bfloat16(f0.z); p1.y = __float2bfloat16(f0.w);
                    p2.x = __float2bfloat16(f1.x); p2.y = __float2bfloat16(f1.y);
                    p3.x = __float2bfloat16(f1.z); p3.y = __float2bfloat16(f1.w);
                    val.x = *(uint32_t*)&p0; val.y = *(uint32_t*)&p1;
                    val.z = *(uint32_t*)&p2; val.w = *(uint32_t*)&p3;
                } else {
                    val = *(const uint4*)((const __nv_bfloat16*)Ain +
                                          (size_t)gr * K + k0);
                }
            }
            *(uint4*)(As + r * LDS + k0) = val;
        }
    }
    __syncthreads();

    uint32_t sA = smem_u32(As);
    uint32_t sW = smem_u32(Ws);
    int lr = lane & 15;
    int lc = (lane >> 4) * 8;
    int groupID = lane >> 2;
    int qcol = (lane & 3) * 2;

    for (int cb = 0; cb < N / 64; cb++) {
        int colBase = cb * 64;
        if (cb) __syncthreads();  // prior chunk's ldsm reads done
        // ---- stage W chunk (64 x K) ----
        {
            constexpr int K8 = K / 8;
            for (int v = tid; v < 64 * K8; v += 256) {
                int r = v / K8;
                int k0 = (v - r * K8) * 8;
                *(uint4*)(Ws + r * LDS + k0) =
                    *(const uint4*)(Wt + (size_t)(colBase + r) * K + k0);
            }
        }
        __syncthreads();

        float acc[2][4][4] = {};
#pragma unroll
        for (int k0 = 0; k0 < K; k0 += 16) {
            uint32_t af[2][4], bf[2][4];
#pragma unroll
            for (int mt = 0; mt < 2; mt++) {
                uint32_t addr =
                    sA + ((warpM + mt * 16 + lr) * LDS + k0 + lc) * 2;
                ldsm_x4(af[mt], addr);
            }
#pragma unroll
            for (int nh = 0; nh < 2; nh++) {
                uint32_t addr =
                    sW + ((warpN + nh * 16 + lr) * LDS + k0 + lc) * 2;
                ldsm_x4(bf[nh], addr);  // Ws is [n][k], k-contiguous
            }
#pragma unroll
            for (int mt = 0; mt < 2; mt++) {
#pragma unroll
                for (int nh = 0; nh < 2; nh++) {
                    mma_bf16(acc[mt][nh * 2 + 0], af[mt], bf[nh][0], bf[nh][2]);
                    mma_bf16(acc[mt][nh * 2 + 1], af[mt], bf[nh][1], bf[nh][3]);
                }
            }
        }

        // ---- epilogue ----
#pragma unroll
        for (int mt = 0; mt < 2; mt++) {
#pragma unroll
            for (int half = 0; half < 2; half++) {
                int row = rowBase + warpM + mt * 16 + groupID + half * 8;
                if (row < n) {
                    uint32_t* orow = (uint32_t*)(C + (size_t)row * N + colBase);
#pragma unroll
                    for (int nt = 0; nt < 4; nt++) {
                        __nv_bfloat162 b2;
                        b2.x = __float2bfloat16(acc[mt][nt][half * 2 + 0]);
                        b2.y = __float2bfloat16(acc[mt][nt][half * 2 + 1]);
                        orow[(warpN + nt * 8 + qcol) >> 1] = *(uint32_t*)&b2;
                    }
                }
            }
        }
    }
}

// ======================= aggregation (bf16 gather, z-batched) =============
template <int M>
__global__ __launch_bounds__(256) void agg_kernel(
    PtrsIn h3, const float* __restrict__ bias, PtrsOut out3) {
    int z = blockIdx.z;
    int warp = blockIdx.x * 8 + (threadIdx.x >> 5);
    int lane = threadIdx.x & 31;
    if (warp >= NN) return;
    constexpr int U = M / 64;

    const __nv_bfloat16* h = (const __nv_bfloat16*)h3.a[z];
    __nv_bfloat16* out = (__nv_bfloat16*)out3.o[z];

    float dv = g_dis[z][warp];
    float dd = dv * dv;
    const uint32_t* hi = (const uint32_t*)(h + (size_t)warp * M);
    float acc[2 * U];
#pragma unroll
    for (int j = 0; j < U; j++) {
        uint32_t u = hi[lane + 32 * j];
        float2 f = __bfloat1622float2(*(__nv_bfloat162*)&u);
        int c = 2 * (lane + 32 * j);
        acc[2 * j]     = f.x * dd + bias[c];
        acc[2 * j + 1] = f.y * dd + bias[c + 1];
    }

    int e0 = g_rowptr[z][warp];
    int e1 = g_rowptr[z][warp + 1];
    for (int e = e0; e < e1; e++) {
        int s = g_csrc[z][e];
        float w = g_cw[z][e];
        const uint32_t* hs = (const uint32_t*)(h + (size_t)s * M);
#pragma unroll
        for (int j = 0; j < U; j++) {
            uint32_t u = __ldg(&hs[lane + 32 * j]);
            float2 f = __bfloat1622float2(*(__nv_bfloat162*)&u);
            acc[2 * j]     = fmaf(w, f.x, acc[2 * j]);
            acc[2 * j + 1] = fmaf(w, f.y, acc[2 * j + 1]);
        }
    }

    uint32_t* oi = (uint32_t*)(out + (size_t)warp * M);
#pragma unroll
    for (int j = 0; j < U; j++) {
        __nv_bfloat162 b2;
        b2.x = __float2bfloat16(fmaxf(acc[2 * j], 0.0f));
        b2.y = __float2bfloat16(fmaxf(acc[2 * j + 1], 0.0f));
        oi[lane + 32 * j] = *(uint32_t*)&b2;
    }
}

// layer-3 agg (M=64) fused with relu + block partial sum (no bf16 round)
__global__ __launch_bounds__(256) void agg3_kernel(
    PtrsIn h3, const float* __restrict__ bias) {
    int z = blockIdx.z;
    int wlocal = threadIdx.x >> 5;
    int warp = blockIdx.x * 8 + wlocal;
    int lane = threadIdx.x & 31;

    const __nv_bfloat16* h = (const __nv_bfloat16*)h3.a[z];
    float s = 0.0f;
    if (warp < NN) {
        float dv = g_dis[z][warp];
        float dd = dv * dv;
        const uint32_t* hi = (const uint32_t*)(h + (size_t)warp * 64);
        uint32_t u = hi[lane];
        float2 f = __bfloat1622float2(*(__nv_bfloat162*)&u);
        int c = 2 * lane;
        float a0 = f.x * dd + bias[c];
        float a1 = f.y * dd + bias[c + 1];

        int e0 = g_rowptr[z][warp];
        int e1 = g_rowptr[z][warp + 1];
        for (int e = e0; e < e1; e++) {
            int src = g_csrc[z][e];
            float w = g_cw[z][e];
            uint32_t us = __ldg((const uint32_t*)(h + (size_t)src * 64) + lane);
            float2 fs = __bfloat1622float2(*(__nv_bfloat162*)&us);
            a0 = fmaf(w, fs.x, a0);
            a1 = fmaf(w, fs.y, a1);
        }
        s = fmaxf(a0, 0.0f) + fmaxf(a1, 0.0f);
    }
#pragma unroll
    for (int o = 16; o; o >>= 1) s += __shfl_down_sync(0xFFFFFFFFu, s, o);
    __shared__ float ws[8];
    if (lane == 0) ws[wlocal] = s;
    __syncthreads();
    if (threadIdx.x < 8) {
        float t = ws[threadIdx.x];
#pragma unroll
        for (int o = 4; o; o >>= 1) t += __shfl_down_sync(0xFFu, t, o);
        if (threadIdx.x == 0) g_part[z * AGG_BLKS + blockIdx.x] = t;
    }
}

__global__ void final_reduce_kernel(float* __restrict__ out) {
    float s = 0.0f;
    for (int i = threadIdx.x; i < 3 * AGG_BLKS; i += 1024) s += g_part[i];
#pragma unroll
    for (int o = 16; o; o >>= 1) s += __shfl_down_sync(0xFFFFFFFFu, s, o);
    __shared__ float ws[32];
    if ((threadIdx.x & 31) == 0) ws[threadIdx.x >> 5] = s;
    __syncthreads();
    if (threadIdx.x < 32) {
        float t = ws[threadIdx.x];
#pragma unroll
        for (int o = 16; o; o >>= 1) t += __shfl_down_sync(0xFFFFFFFFu, t, o);
        if (threadIdx.x == 0) out[0] = t * (1.0f / 64.0f);
    }
}

// ======================= launcher =======================
extern "C" void kernel_launch(void* const* d_in, const int* in_sizes, int n_in,
                              void* d_out, int out_size) {
    float* out = (float*)d_out;

    Edges eg;
    int Emax = 0;
    for (int g = 0; g < 3; g++) {
        eg.e[g] = (const int*)d_in[3 + g];
        eg.E[g] = in_sizes[3 + g] / 2;
        if (eg.E[g] > Emax) Emax = eg.E[g];
    }

    __nv_bfloat16 *ph, *pa, *pw1, *pw2, *pw3;
    cudaGetSymbolAddress((void**)&ph, g_h);
    cudaGetSymbolAddress((void**)&pa, g_a);
    cudaGetSymbolAddress((void**)&pw1, g_Wt1);
    cudaGetSymbolAddress((void**)&pw2, g_Wt2);
    cudaGetSymbolAddress((void**)&pw3, g_Wt3);

    PtrsIn xin, hin, ain;
    PtrsOut hout, aout;
    for (int g = 0; g < 3; g++) {
        xin.a[g] = d_in[g];
        hin.a[g] = ph + (size_t)g * NN * 256;
        ain.a[g] = pa + (size_t)g * NN * 256;
        hout.o[g] = ph + (size_t)g * NN * 256;
        aout.o[g] = pa + (size_t)g * NN * 256;
    }

    const int SM256 = 192 * (256 + 8) * 2;  // 101376
    const int SM128 = 192 * (128 + 8) * 2;  // 52224
    cudaFuncSetAttribute(gemm_mma_kernel<true, 256, 256>,
                         cudaFuncAttributeMaxDynamicSharedMemorySize, SM256);
    cudaFuncSetAttribute(gemm_mma_kernel<false, 256, 128>,
                         cudaFuncAttributeMaxDynamicSharedMemorySize, SM256);
    cudaFuncSetAttribute(gemm_mma_kernel<false, 128, 64>,
                         cudaFuncAttributeMaxDynamicSharedMemorySize, SM128);

    const int NB = (NN + 255) / 256;        // 196
    const int GB = (NN + 127) / 128;        // 391
    const int EB = (Emax + 255) / 256;

    wt_all_kernel<<<(106496 + 255) / 256, 256>>>(
        (const float*)d_in[6], (const float*)d_in[8], (const float*)d_in[10]);

    // graph prep (all 3 graphs per launch)
    count_init_kernel<<<dim3(NB, 1, 3), 256>>>();
    count_edges_kernel<<<dim3(EB, 1, 3), 256>>>(eg);
    scan_block_kernel<<<dim3(NB, 1, 3), 256>>>();
    scan_tops_kernel<<<dim3(1, 1, 3), 256>>>(NB);
    scan_add_kernel<<<dim3(NB, 1, 3), 256>>>(eg);
    fill_csr_kernel<<<dim3(EB, 1, 3), 256>>>(eg);

    const float* b1 = (const float*)d_in[7];
    const float* b2 = (const float*)d_in[9];
    const float* b3 = (const float*)d_in[11];

    // layer 1: 256 -> 256
    gemm_mma_kernel<true, 256, 256>
        <<<dim3(GB, 1, 3), 256, SM256>>>(xin, pw1, hout, NN);
    agg_kernel<256><<<dim3(AGG_BLKS, 1, 3), 256>>>(hin, b1, aout);
    // layer 2: 256 -> 128
    gemm_mma_kernel<false, 256, 128>
        <<<dim3(GB, 1, 3), 256, SM256>>>(ain, pw2, hout, NN);
    agg_kernel<128><<<dim3(AGG_BLKS, 1, 3), 256>>>(hin, b2, aout);
    // layer 3: 128 -> 64 (agg fused with reduction)
    gemm_mma_kernel<false, 128, 64>
        <<<dim3(GB, 1, 3), 256, SM128>>>(ain, pw3, hout, NN);
    agg3_kernel<<<dim3(AGG_BLKS, 1, 3), 256>>>(hin, b3);

    final_reduce_kernel<<<1, 1024>>>(out);
}